// round 14
// baseline (speedup 1.0000x reference)
#include <cuda_runtime.h>
#include <math.h>

#define Bsz 4
#define Ssz 2048
#define Dsz 768
#define Hsz 12
#define HDsz 64
#define BH (Bsz*Hsz)          // 48
#define MROWS (Bsz*Ssz)       // 8192
#define N_QKV (3*Dsz)         // 2304

// ---------------- scratch (no allocations allowed) ----------------
__device__ float g_Q[BH * Ssz * HDsz];   // [b,h,s,hd]
__device__ float g_K[BH * Ssz * HDsz];
__device__ float g_V[BH * Ssz * HDsz];
__device__ float g_attn[MROWS * Dsz];    // [b,s, h*64+hd]
__device__ float g_x[MROWS * Dsz];       // proj + bias + residual

// ---------------- bf16 split helpers ----------------
__device__ __forceinline__ float btrunc(float a) {            // bf16 truncate
    return __uint_as_float(__float_as_uint(a) & 0xFFFF0000u);
}
__device__ __forceinline__ unsigned packbf(float ah, float bh) { // both pre-truncated
    return (__float_as_uint(ah) >> 16) | (__float_as_uint(bh) & 0xFFFF0000u);
}
__device__ __forceinline__ void splitp(float a, float b, unsigned& hp, unsigned& lp) {
    float ah = btrunc(a), bh = btrunc(b);
    hp = packbf(ah, bh);
    lp = packbf(btrunc(a - ah), btrunc(b - bh));
}
__device__ __forceinline__ void mmabf(float c[4], const unsigned a[4],
                                      unsigned b0, unsigned b1) {
    asm volatile(
        "mma.sync.aligned.m16n8k16.row.col.f32.bf16.bf16.f32 "
        "{%0,%1,%2,%3}, {%4,%5,%6,%7}, {%8,%9}, {%0,%1,%2,%3};\n"
        : "+f"(c[0]), "+f"(c[1]), "+f"(c[2]), "+f"(c[3])
        : "r"(a[0]), "r"(a[1]), "r"(a[2]), "r"(a[3]), "r"(b0), "r"(b1));
}

// ============================================================
// bf16x3 GEMM core: block 128x64, BK=32, 256 thr, warp tile 32x32.
// (R13 version: prefetch + B-fragment reuse — proven)
// ============================================================
__device__ __forceinline__ void bf3_core(
    const float* __restrict__ A, const float* __restrict__ Bw,
    int NN, int m0, int n0, float acc[2][4][4],
    unsigned AH[128][17], unsigned AL[128][17],
    unsigned BHs[64][17], unsigned BLs[64][17])
{
    const int tid  = threadIdx.x;
    const int lane = tid & 31, wid = tid >> 5;
    const int g = lane >> 2, tig = lane & 3;
    const int wm = wid >> 1, wn = wid & 1;

    const int mA = tid >> 1, kqA = (tid & 1) * 16;
    const float* Ap = A + (size_t)(m0 + mA) * Dsz + kqA;
    const int kpB = tid >> 4, nqB = (tid & 15) * 4;
    const float* Bp = Bw + (size_t)(2 * kpB) * NN + n0 + nqB;

#pragma unroll
    for (int i = 0; i < 2; i++)
#pragma unroll
        for (int j = 0; j < 4; j++)
#pragma unroll
            for (int r = 0; r < 4; r++) acc[i][j][r] = 0.f;

    float4 a0 = *(const float4*)(Ap);
    float4 a1 = *(const float4*)(Ap + 4);
    float4 a2 = *(const float4*)(Ap + 8);
    float4 a3 = *(const float4*)(Ap + 12);
    float4 b0 = *(const float4*)(Bp);
    float4 b1 = *(const float4*)(Bp + NN);

#pragma unroll 1
    for (int it = 0; it < Dsz / 32; it++) {
        const int kp = kqA >> 1;
        splitp(a0.x, a0.y, AH[mA][kp+0], AL[mA][kp+0]);
        splitp(a0.z, a0.w, AH[mA][kp+1], AL[mA][kp+1]);
        splitp(a1.x, a1.y, AH[mA][kp+2], AL[mA][kp+2]);
        splitp(a1.z, a1.w, AH[mA][kp+3], AL[mA][kp+3]);
        splitp(a2.x, a2.y, AH[mA][kp+4], AL[mA][kp+4]);
        splitp(a2.z, a2.w, AH[mA][kp+5], AL[mA][kp+5]);
        splitp(a3.x, a3.y, AH[mA][kp+6], AL[mA][kp+6]);
        splitp(a3.z, a3.w, AH[mA][kp+7], AL[mA][kp+7]);
        splitp(b0.x, b1.x, BHs[nqB+0][kpB], BLs[nqB+0][kpB]);
        splitp(b0.y, b1.y, BHs[nqB+1][kpB], BLs[nqB+1][kpB]);
        splitp(b0.z, b1.z, BHs[nqB+2][kpB], BLs[nqB+2][kpB]);
        splitp(b0.w, b1.w, BHs[nqB+3][kpB], BLs[nqB+3][kpB]);
        __syncthreads();

        if (it + 1 < Dsz / 32) {
            const int k1 = (it + 1) * 32;
            a0 = *(const float4*)(Ap + k1);
            a1 = *(const float4*)(Ap + k1 + 4);
            a2 = *(const float4*)(Ap + k1 + 8);
            a3 = *(const float4*)(Ap + k1 + 12);
            b0 = *(const float4*)(Bp + (size_t)k1 * NN);
            b1 = *(const float4*)(Bp + (size_t)k1 * NN + NN);
        }

#pragma unroll
        for (int ks = 0; ks < 2; ks++) {
            const int kb = ks * 8;
            unsigned aH[2][4], aL[2][4];
#pragma unroll
            for (int mf = 0; mf < 2; mf++) {
                const int row = wm * 32 + mf * 16 + g;
                aH[mf][0] = AH[row][kb + tig];         aL[mf][0] = AL[row][kb + tig];
                aH[mf][1] = AH[row + 8][kb + tig];     aL[mf][1] = AL[row + 8][kb + tig];
                aH[mf][2] = AH[row][kb + 4 + tig];     aL[mf][2] = AL[row][kb + 4 + tig];
                aH[mf][3] = AH[row + 8][kb + 4 + tig]; aL[mf][3] = AL[row + 8][kb + 4 + tig];
            }
#pragma unroll
            for (int nf = 0; nf < 4; nf++) {
                const int n = wn * 32 + nf * 8 + g;
                unsigned bH0 = BHs[n][kb + tig], bH1 = BHs[n][kb + 4 + tig];
                unsigned bL0 = BLs[n][kb + tig], bL1 = BLs[n][kb + 4 + tig];
#pragma unroll
                for (int mf = 0; mf < 2; mf++) {
                    mmabf(acc[mf][nf], aL[mf], bH0, bH1);
                    mmabf(acc[mf][nf], aH[mf], bL0, bL1);
                    mmabf(acc[mf][nf], aH[mf], bH0, bH1);
                }
            }
        }
        __syncthreads();
    }
}

// ---------------- QKV GEMM -> scatter to g_Q/g_K/g_V ----------------
__global__ void __launch_bounds__(256)
qkv_b3(const float* __restrict__ A, const float* __restrict__ Bw)
{
    __shared__ unsigned AH[128][17], AL[128][17];
    __shared__ unsigned BHs[64][17], BLs[64][17];

    const int m0 = blockIdx.y * 128, n0 = blockIdx.x * 64;
    float acc[2][4][4];
    bf3_core(A, Bw, N_QKV, m0, n0, acc, AH, AL, BHs, BLs);

    const int tid = threadIdx.x;
    const int lane = tid & 31, wid = tid >> 5;
    const int g = lane >> 2, tig = lane & 3;
    const int wm = wid >> 1, wn = wid & 1;

    const int nbase = n0 + wn * 32;
    const int which = nbase / Dsz;
    const int h = (nbase % Dsz) >> 6;
    const int hd0 = (nbase % Dsz) & 63;
    float* dst = (which == 0) ? g_Q : (which == 1) ? g_K : g_V;
#pragma unroll
    for (int mf = 0; mf < 2; mf++) {
        const int m = m0 + wm * 32 + mf * 16 + g;
        const int b = m >> 11, s = m & 2047;
        float* r0 = dst + ((size_t)(b * Hsz + h) * Ssz + s) * HDsz + hd0;
        float* r1 = r0 + 8 * HDsz;
#pragma unroll
        for (int nf = 0; nf < 4; nf++) {
            const int hd = nf * 8 + tig * 2;
            *(float2*)(r0 + hd) = make_float2(acc[mf][nf][0], acc[mf][nf][1]);
            *(float2*)(r1 + hd) = make_float2(acc[mf][nf][2], acc[mf][nf][3]);
        }
    }
}

// ---------------- proj GEMM -> g_x = acc + bias + resid ----------------
__global__ void __launch_bounds__(256)
proj_b3(const float* __restrict__ Bw, const float* __restrict__ bias,
        const float* __restrict__ resid)
{
    __shared__ unsigned AH[128][17], AL[128][17];
    __shared__ unsigned BHs[64][17], BLs[64][17];

    const int m0 = blockIdx.y * 128, n0 = blockIdx.x * 64;
    float acc[2][4][4];
    bf3_core(g_attn, Bw, Dsz, m0, n0, acc, AH, AL, BHs, BLs);

    const int tid = threadIdx.x;
    const int lane = tid & 31, wid = tid >> 5;
    const int g = lane >> 2, tig = lane & 3;
    const int wm = wid >> 1, wn = wid & 1;

#pragma unroll
    for (int mf = 0; mf < 2; mf++) {
        const int m = m0 + wm * 32 + mf * 16 + g;
#pragma unroll
        for (int nf = 0; nf < 4; nf++) {
            const int n = n0 + wn * 32 + nf * 8 + tig * 2;
            float2 bv  = *(const float2*)(bias + n);
            float2 rv0 = *(const float2*)(resid + (size_t)m * Dsz + n);
            float2 rv1 = *(const float2*)(resid + (size_t)(m + 8) * Dsz + n);
            *(float2*)(g_x + (size_t)m * Dsz + n) =
                make_float2(acc[mf][nf][0] + bv.x + rv0.x, acc[mf][nf][1] + bv.y + rv0.y);
            *(float2*)(g_x + (size_t)(m + 8) * Dsz + n) =
                make_float2(acc[mf][nf][2] + bv.x + rv1.x, acc[mf][nf][3] + bv.y + rv1.y);
        }
    }
}

// ============================================================
// Flash attention, bf16x3 HMMA. 256 thr (8 warps), q-tile 128
// (warp tile 16 q-rows — R12 per-warp register footprint),
// k-tile 64. K/V load+split amortized over 128 q-rows.
// ============================================================
#define ATTN_SMEM_BYTES ((2*128*33 + 2*64*33 + 64*66 + 64) * 4)  // 67840 B

__global__ void __launch_bounds__(256)
fa_tc3(const float* __restrict__ pad_mask)
{
    extern __shared__ unsigned smu[];
    unsigned* QsH = smu;                     // [128][33] packed k-pairs
    unsigned* QsL = QsH + 128 * 33;
    unsigned* KsH = QsL + 128 * 33;          // [64][33]
    unsigned* KsL = KsH + 64 * 33;
    unsigned short* VtH = (unsigned short*)(KsL + 64 * 33);  // bf16 [64][66]
    unsigned short* VtL = VtH + 64 * 66;
    float* msk = (float*)(smu + 2 * 128 * 33 + 2 * 64 * 33 + 64 * 66);

    const int tid  = threadIdx.x;
    const int lane = tid & 31, wid = tid >> 5;
    const int g = lane >> 2, tig = lane & 3;
    const int qw = wid * 16;                 // warp q-row base (0..112)
    const int q0 = blockIdx.x * 128;
    const int bh = blockIdx.y;
    const int b = bh / Hsz, h = bh % Hsz;

    const float* Qg = g_Q + ((size_t)bh * Ssz + q0) * HDsz;
    const float* Kg = g_K + (size_t)bh * Ssz * HDsz;
    const float* Vg = g_V + (size_t)bh * Ssz * HDsz;
    const float* mk = pad_mask + b * Ssz;

    // ---- load Q tile (scaled by 1/8), split into packed hi/lo k-pairs ----
#pragma unroll
    for (int i = 0; i < 8; i++) {
        int idx = tid + i * 256;
        int r = idx >> 4, c4 = (idx & 15) * 4;
        float4 v = *(const float4*)(Qg + r * HDsz + c4);
        v.x *= 0.125f; v.y *= 0.125f; v.z *= 0.125f; v.w *= 0.125f;
        int kp = r * 33 + (c4 >> 1);
        splitp(v.x, v.y, QsH[kp],     QsL[kp]);
        splitp(v.z, v.w, QsH[kp + 1], QsL[kp + 1]);
    }

    float O[8][4];
#pragma unroll
    for (int i = 0; i < 8; i++)
#pragma unroll
        for (int j = 0; j < 4; j++) O[i][j] = 0.f;
    float m0r = -1e30f, m1r = -1e30f, l0 = 0.f, l1 = 0.f;

#pragma unroll 1
    for (int kt = 0; kt < Ssz / 64; kt++) {
        const int key0 = kt * 64;
        __syncthreads();
#pragma unroll
        for (int i = 0; i < 4; i++) {
            int idx = tid + i * 256;
            int r = idx >> 4, c4 = (idx & 15) * 4;
            float4 kv = *(const float4*)(Kg + (size_t)(key0 + r) * HDsz + c4);
            int kp = r * 33 + (c4 >> 1);
            splitp(kv.x, kv.y, KsH[kp],     KsL[kp]);
            splitp(kv.z, kv.w, KsH[kp + 1], KsL[kp + 1]);
            float4 vv = *(const float4*)(Vg + (size_t)(key0 + r) * HDsz + c4);
#pragma unroll
            for (int q = 0; q < 4; q++) {
                float x = (&vv.x)[q];
                float hh = btrunc(x);
                VtH[(c4 + q) * 66 + r] = (unsigned short)(__float_as_uint(hh) >> 16);
                VtL[(c4 + q) * 66 + r] = (unsigned short)(__float_as_uint(btrunc(x - hh)) >> 16);
            }
        }
        if (tid < 64) msk[tid] = mk[key0 + tid];
        __syncthreads();

        // ---- S = Q @ K^T (bf16x3) ----
        float sacc[8][4];
#pragma unroll
        for (int i = 0; i < 8; i++)
#pragma unroll
            for (int j = 0; j < 4; j++) sacc[i][j] = 0.f;
#pragma unroll 1
        for (int ks = 0; ks < 4; ks++) {
            const int kb = ks * 8;
            const int row = qw + g;
            unsigned aH[4], aL[4];
            aH[0] = QsH[row * 33 + kb + tig];
            aH[1] = QsH[(row + 8) * 33 + kb + tig];
            aH[2] = QsH[row * 33 + kb + 4 + tig];
            aH[3] = QsH[(row + 8) * 33 + kb + 4 + tig];
            aL[0] = QsL[row * 33 + kb + tig];
            aL[1] = QsL[(row + 8) * 33 + kb + tig];
            aL[2] = QsL[row * 33 + kb + 4 + tig];
            aL[3] = QsL[(row + 8) * 33 + kb + 4 + tig];
#pragma unroll
            for (int nf = 0; nf < 8; nf++) {
                const int n = nf * 8 + g;
                unsigned bH0 = KsH[n * 33 + kb + tig];
                unsigned bH1 = KsH[n * 33 + kb + 4 + tig];
                unsigned bL0 = KsL[n * 33 + kb + tig];
                unsigned bL1 = KsL[n * 33 + kb + 4 + tig];
                mmabf(sacc[nf], aL, bH0, bH1);
                mmabf(sacc[nf], aH, bL0, bL1);
                mmabf(sacc[nf], aH, bH0, bH1);
            }
        }

        // ---- mask (scale folded into Q) ----
#pragma unroll
        for (int nf = 0; nf < 8; nf++) {
            float mv0 = msk[nf * 8 + tig * 2];
            float mv1 = msk[nf * 8 + tig * 2 + 1];
            sacc[nf][0] = sacc[nf][0] * mv0 - (1.f - mv0) * 1e10f;
            sacc[nf][1] = sacc[nf][1] * mv1 - (1.f - mv1) * 1e10f;
            sacc[nf][2] = sacc[nf][2] * mv0 - (1.f - mv0) * 1e10f;
            sacc[nf][3] = sacc[nf][3] * mv1 - (1.f - mv1) * 1e10f;
        }

        // ---- online softmax (rows qw+g and qw+g+8) ----
        float tm0 = -1e30f, tm1 = -1e30f;
#pragma unroll
        for (int nf = 0; nf < 8; nf++) {
            tm0 = fmaxf(tm0, fmaxf(sacc[nf][0], sacc[nf][1]));
            tm1 = fmaxf(tm1, fmaxf(sacc[nf][2], sacc[nf][3]));
        }
        tm0 = fmaxf(tm0, __shfl_xor_sync(0xffffffffu, tm0, 1));
        tm0 = fmaxf(tm0, __shfl_xor_sync(0xffffffffu, tm0, 2));
        tm1 = fmaxf(tm1, __shfl_xor_sync(0xffffffffu, tm1, 1));
        tm1 = fmaxf(tm1, __shfl_xor_sync(0xffffffffu, tm1, 2));
        float mn0 = fmaxf(m0r, tm0), mn1 = fmaxf(m1r, tm1);
        float c0 = __expf(m0r - mn0), c1 = __expf(m1r - mn1);
        float s0 = 0.f, s1 = 0.f;
#pragma unroll
        for (int nf = 0; nf < 8; nf++) {
            sacc[nf][0] = __expf(sacc[nf][0] - mn0);
            sacc[nf][1] = __expf(sacc[nf][1] - mn0);
            sacc[nf][2] = __expf(sacc[nf][2] - mn1);
            sacc[nf][3] = __expf(sacc[nf][3] - mn1);
            s0 += sacc[nf][0] + sacc[nf][1];
            s1 += sacc[nf][2] + sacc[nf][3];
        }
        s0 += __shfl_xor_sync(0xffffffffu, s0, 1);
        s0 += __shfl_xor_sync(0xffffffffu, s0, 2);
        s1 += __shfl_xor_sync(0xffffffffu, s1, 1);
        s1 += __shfl_xor_sync(0xffffffffu, s1, 2);
        l0 = l0 * c0 + s0;
        l1 = l1 * c1 + s1;
        m0r = mn0; m1r = mn1;
#pragma unroll
        for (int nf = 0; nf < 8; nf++) {
            O[nf][0] *= c0; O[nf][1] *= c0;
            O[nf][2] *= c1; O[nf][3] *= c1;
        }

        // ---- O += P @ V (bf16x3, P in registers) ----
#pragma unroll 1
        for (int ks = 0; ks < 4; ks++) {
            unsigned aPH[4], aPL[4];
            splitp(sacc[2 * ks][0],     sacc[2 * ks][1],     aPH[0], aPL[0]);
            splitp(sacc[2 * ks][2],     sacc[2 * ks][3],     aPH[1], aPL[1]);
            splitp(sacc[2 * ks + 1][0], sacc[2 * ks + 1][1], aPH[2], aPL[2]);
            splitp(sacc[2 * ks + 1][2], sacc[2 * ks + 1][3], aPH[3], aPL[3]);
            const int kb = ks * 16 + 2 * tig;
#pragma unroll
            for (int nf = 0; nf < 8; nf++) {
                const int n = nf * 8 + g;
                unsigned bH0 = *(const unsigned*)(VtH + n * 66 + kb);
                unsigned bH1 = *(const unsigned*)(VtH + n * 66 + kb + 8);
                unsigned bL0 = *(const unsigned*)(VtL + n * 66 + kb);
                unsigned bL1 = *(const unsigned*)(VtL + n * 66 + kb + 8);
                mmabf(O[nf], aPL, bH0, bH1);
                mmabf(O[nf], aPH, bL0, bL1);
                mmabf(O[nf], aPH, bH0, bH1);
            }
        }
    }

    // ---- epilogue -> g_attn[b,s,h*64+hd] ----
    const float inv0 = 1.f / l0, inv1 = 1.f / l1;
    const int s0r = q0 + qw + g, s1r = s0r + 8;
    float* r0 = g_attn + ((size_t)b * Ssz + s0r) * Dsz + h * HDsz;
    float* r1 = g_attn + ((size_t)b * Ssz + s1r) * Dsz + h * HDsz;
#pragma unroll
    for (int nf = 0; nf < 8; nf++) {
        const int hd = nf * 8 + tig * 2;
        *(float2*)(r0 + hd) = make_float2(O[nf][0] * inv0, O[nf][1] * inv0);
        *(float2*)(r1 + hd) = make_float2(O[nf][2] * inv1, O[nf][3] * inv1);
    }
}

// ---------------- LayerNorm over rows of 768 ----------------
__global__ void ln_v2(const float* __restrict__ gamma,
                      const float* __restrict__ beta,
                      float* __restrict__ out)
{
    __shared__ float red[256];
    const int row = blockIdx.x;
    const int t = threadIdx.x;
    const float* xr = g_x + (size_t)row * Dsz;

    float v[3];
    float s = 0.f;
#pragma unroll
    for (int i = 0; i < 3; i++) { v[i] = xr[t + i * 256]; s += v[i]; }
    red[t] = s; __syncthreads();
#pragma unroll
    for (int off = 128; off > 0; off >>= 1) {
        if (t < off) red[t] += red[t + off];
        __syncthreads();
    }
    float mean = red[0] * (1.f / 768.f);
    __syncthreads();

    float s2 = 0.f;
#pragma unroll
    for (int i = 0; i < 3; i++) { float d = v[i] - mean; s2 += d * d; }
    red[t] = s2; __syncthreads();
#pragma unroll
    for (int off = 128; off > 0; off >>= 1) {
        if (t < off) red[t] += red[t + off];
        __syncthreads();
    }
    float var = red[0] * (1.f / 768.f);
    float inv = rsqrtf(var + 1e-5f);

    float* orow = out + (size_t)row * Dsz;
#pragma unroll
    for (int i = 0; i < 3; i++) {
        int c = t + i * 256;
        orow[c] = (v[i] - mean) * inv * gamma[c] + beta[c];
    }
}

// ---------------- launch ----------------
extern "C" void kernel_launch(void* const* d_in, const int* in_sizes, int n_in,
                              void* d_out, int out_size)
{
    const float* context  = (const float*)d_in[0];
    const float* pad_mask = (const float*)d_in[1];
    const float* w_qkv    = (const float*)d_in[2];
    const float* w_proj   = (const float*)d_in[3];
    const float* b_proj   = (const float*)d_in[4];
    const float* gamma    = (const float*)d_in[5];
    const float* beta     = (const float*)d_in[6];
    float* out = (float*)d_out;

    cudaFuncSetAttribute(fa_tc3, cudaFuncAttributeMaxDynamicSharedMemorySize,
                         ATTN_SMEM_BYTES);

    qkv_b3<<<dim3(N_QKV / 64, MROWS / 128), 256>>>(context, w_qkv);
    fa_tc3<<<dim3(Ssz / 128, BH), 256, ATTN_SMEM_BYTES>>>(pad_mask);
    proj_b3<<<dim3(Dsz / 64, MROWS / 128), 256>>>(w_proj, b_proj, context);
    ln_v2<<<MROWS, 256>>>(gamma, beta, out);
}